// round 14
// baseline (speedup 1.0000x reference)
#include <cuda_runtime.h>
#include <cuda_bf16.h>
#include <cstdint>

typedef unsigned long long ull;

#define T_ 1024
#define I_ 128
#define H_ 512
#define O_ 512
#define M_ 32768

// ---------------- device scratch ----------------
__device__ float d_U[T_ * H_];
__device__ float d_Lx[(size_t)M_ * T_];
__device__ float d_Lg[(size_t)M_ * T_];
__device__ float d_nx[M_];
__device__ float d_ng[M_];
__device__ float d_bsum[H_];
__device__ float d_hstate[H_];
__device__ __nv_bfloat16 d_xv_hi[(size_t)M_ * 512];
__device__ __nv_bfloat16 d_gk_hi[(size_t)M_ * 512];
__device__ __nv_bfloat16 d_qx_hi[(size_t)T_ * 512];
__device__ __nv_bfloat16 d_qg_hi[(size_t)T_ * 512];

// ---------------- helpers ----------------
__device__ __forceinline__ uint32_t smem_u32(const void* p) {
    uint32_t a;
    asm("{ .reg .u64 t; cvta.to.shared.u64 t, %1; cvt.u32.u64 %0, t; }" : "=r"(a) : "l"(p));
    return a;
}
__device__ __forceinline__ void ffma2(ull& d, ull a, ull b) {
    asm("fma.rn.f32x2 %0, %1, %2, %0;" : "+l"(d) : "l"(a), "l"(b));
}
__device__ __forceinline__ ull pack2(float x, float y) {
    ull r; asm("mov.b64 %0, {%1,%2};" : "=l"(r) : "f"(x), "f"(y)); return r;
}
__device__ __forceinline__ void unpack2(float& lo, float& hi, ull v) {
    asm("mov.b64 {%0,%1}, %2;" : "=f"(lo), "=f"(hi) : "l"(v));
}
__device__ __forceinline__ void cpa16(uint32_t s, const void* g) {
    asm volatile("cp.async.cg.shared.global [%0], [%1], 16;" :: "r"(s), "l"(g));
}
__device__ __forceinline__ void ldm_x4(uint32_t& r0, uint32_t& r1, uint32_t& r2, uint32_t& r3,
                                       uint32_t addr) {
    asm volatile("ldmatrix.sync.aligned.m8n8.x4.shared.b16 {%0,%1,%2,%3}, [%4];"
                 : "=r"(r0), "=r"(r1), "=r"(r2), "=r"(r3) : "r"(addr));
}
__device__ __forceinline__ void ldm_x2(uint32_t& r0, uint32_t& r1, uint32_t addr) {
    asm volatile("ldmatrix.sync.aligned.m8n8.x2.shared.b16 {%0,%1}, [%2];"
                 : "=r"(r0), "=r"(r1) : "r"(addr));
}
__device__ __forceinline__ void mma_bf16(float& c0, float& c1, float& c2, float& c3,
                                         uint32_t a0, uint32_t a1, uint32_t a2, uint32_t a3,
                                         uint32_t b0, uint32_t b1) {
    asm volatile(
        "mma.sync.aligned.m16n8k16.row.col.f32.bf16.bf16.f32 "
        "{%0,%1,%2,%3}, {%4,%5,%6,%7}, {%8,%9}, {%0,%1,%2,%3};"
        : "+f"(c0), "+f"(c1), "+f"(c2), "+f"(c3)
        : "r"(a0), "r"(a1), "r"(a2), "r"(a3), "r"(b0), "r"(b1));
}

// ---------------- prologue ----------------
__global__ void bsum_kernel(const float* __restrict__ a, const float* __restrict__ b,
                            float* __restrict__ o) {
    int i = threadIdx.x; o[i] = a[i] + b[i];
}

__global__ void prep_patterns(const float* __restrict__ P,
                              __nv_bfloat16* __restrict__ xh, __nv_bfloat16* __restrict__ gh,
                              float* __restrict__ nx, float* __restrict__ ng) {
    __shared__ float s_nx, s_ng;
    int row = blockIdx.x;
    int c = threadIdx.x;
    if (c == 0) { s_nx = 0.f; s_ng = 0.f; }
    __syncthreads();
    float4 v = reinterpret_cast<const float4*>(P + (size_t)row * 1024)[c];
    float f[4] = {v.x, v.y, v.z, v.w};
    float sq = f[0] * f[0] + f[1] * f[1] + f[2] * f[2] + f[3] * f[3];
    __nv_bfloat16 h[4];
#pragma unroll
    for (int j = 0; j < 4; j++) h[j] = __float2bfloat16(f[j]);
    int col = c * 4;
    __nv_bfloat16* dh; size_t off;
    if (col < 512) { dh = xh; off = (size_t)row * 512 + col; }
    else           { dh = gh; off = (size_t)row * 512 + col - 512; }
    reinterpret_cast<__nv_bfloat162*>(dh + off)[0] = __nv_bfloat162(h[0], h[1]);
    reinterpret_cast<__nv_bfloat162*>(dh + off)[1] = __nv_bfloat162(h[2], h[3]);
#pragma unroll
    for (int o = 16; o; o >>= 1) sq += __shfl_xor_sync(0xffffffffu, sq, o);
    if ((threadIdx.x & 31) == 0) {
        if (col < 512) atomicAdd(&s_nx, sq); else atomicAdd(&s_ng, sq);
    }
    __syncthreads();
    if (c == 0) { nx[row] = s_nx; ng[row] = s_ng; }
}

__global__ void split_q(const float* __restrict__ X, __nv_bfloat16* __restrict__ hi) {
    int row = blockIdx.x;
    int c = threadIdx.x;
    float4 v = reinterpret_cast<const float4*>(X + (size_t)row * 512)[c];
    __nv_bfloat16 h[4] = {__float2bfloat16(v.x), __float2bfloat16(v.y),
                          __float2bfloat16(v.z), __float2bfloat16(v.w)};
    size_t off = (size_t)row * 512 + c * 4;
    reinterpret_cast<__nv_bfloat162*>(hi + off)[0] = __nv_bfloat162(h[0], h[1]);
    reinterpret_cast<__nv_bfloat162*>(hi + off)[1] = __nv_bfloat162(h[2], h[3]);
}

// ---------------- fp32 f32x2 GEMM (U precompute, K=128) ----------------
#define PADK 36
__global__ void __launch_bounds__(256, 1)
gemm_nt(const float* __restrict__ A, int lda,
        const float* __restrict__ B, int ldb,
        const float* __restrict__ vec, float alpha, float vc,
        float* __restrict__ C, int ldc, int K) {
    extern __shared__ float smf[];
    float* AsBase = smf;
    float* BsBase = smf + 2 * 128 * PADK;
    const int tid = threadIdx.x;
    const int tx = tid & 15, ty = tid >> 4;
    const int m0 = blockIdx.x << 7, n0 = blockIdx.y << 7;
    const int lrow = tid >> 3, lq = tid & 7;
    const uint32_t sA = smem_u32(AsBase), sB = smem_u32(BsBase);

    ull acc[64];
#pragma unroll
    for (int i = 0; i < 64; i++) acc[i] = 0ULL;

    auto issue = [&](int buf, int k0) {
        uint32_t da = sA + (uint32_t)buf * (128 * PADK * 4);
        uint32_t db = sB + (uint32_t)buf * (128 * PADK * 4);
#pragma unroll
        for (int l = 0; l < 4; l++) {
            int row = lrow + (l << 5);
            uint32_t so = (((uint32_t)(row * PADK) + (uint32_t)(lq << 2)) << 2);
            cpa16(da + so, A + (size_t)(m0 + row) * lda + k0 + (lq << 2));
            cpa16(db + so, B + (size_t)(n0 + row) * ldb + k0 + (lq << 2));
        }
        asm volatile("cp.async.commit_group;" ::: "memory");
    };

    const int nch = K >> 5;
    issue(0, 0);
    asm volatile("cp.async.wait_group 0;" ::: "memory");
    __syncthreads();

    for (int c = 0; c < nch; ++c) {
        if (c + 1 < nch) issue((c + 1) & 1, (c + 1) << 5);
        const float* As = AsBase + (c & 1) * (128 * PADK);
        const float* Bs = BsBase + (c & 1) * (128 * PADK);
#pragma unroll
        for (int k2 = 0; k2 < 16; k2++) {
            const int k = k2 << 1;
            ull a2[8], b2[8];
#pragma unroll
            for (int i = 0; i < 8; i++)
                a2[i] = *reinterpret_cast<const ull*>(As + ((i << 4) + ty) * PADK + k);
#pragma unroll
            for (int j = 0; j < 8; j++)
                b2[j] = *reinterpret_cast<const ull*>(Bs + ((j << 4) + tx) * PADK + k);
#pragma unroll
            for (int i = 0; i < 8; i++)
#pragma unroll
                for (int j = 0; j < 8; j++)
                    ffma2(acc[(i << 3) + j], a2[i], b2[j]);
        }
        asm volatile("cp.async.wait_group 0;" ::: "memory");
        __syncthreads();
    }

#pragma unroll
    for (int i = 0; i < 8; i++) {
        int m = m0 + (i << 4) + ty;
#pragma unroll
        for (int j = 0; j < 8; j++) {
            int n = n0 + (j << 4) + tx;
            float lo, hi; unpack2(lo, hi, acc[(i << 3) + j]);
            C[(size_t)m * ldc + n] = alpha * (lo + hi) + vc * vec[n];
        }
    }
}

// ---------------- single-pass bf16 HMMA GEMM (chunkable in m) ----------------
#define PITCH 80
#define MATB  (128 * PITCH)
#define STG1  (2 * MATB)

__global__ void __launch_bounds__(256, 1)
gemm1p(const __nv_bfloat16* __restrict__ A, const __nv_bfloat16* __restrict__ B,
       const float* __restrict__ vec, float alpha, float vc,
       float* __restrict__ C, int ldc, int m_span, int m_base) {
    extern __shared__ char sm[];
    const uint32_t sb0 = smem_u32(sm);
    const int tid = threadIdx.x, wid = tid >> 5, lane = tid & 31;
    const int wm = wid >> 2, wn = wid & 3;
    const int gi = blockIdx.x;
    const int m0 = (m_base + (gi % m_span)) << 7, n0 = (gi / m_span) << 7;

    float acc[4][4][4];
#pragma unroll
    for (int i = 0; i < 4; i++)
#pragma unroll
        for (int j = 0; j < 4; j++)
#pragma unroll
            for (int k = 0; k < 4; k++) acc[i][j][k] = 0.f;

    auto issue = [&](int stage, int k0) {
        uint32_t base = sb0 + stage * STG1;
#pragma unroll
        for (int t = 0; t < 2; t++) {
            const __nv_bfloat16* G = t ? B : A;
            int r0 = t ? n0 : m0;
#pragma unroll
            for (int q = 0; q < 2; q++) {
                int idx = tid + (q << 8);
                int row = idx >> 2, seg = idx & 3;
                cpa16(base + t * MATB + row * PITCH + seg * 16,
                      G + (size_t)(r0 + row) * 512 + k0 + seg * 8);
            }
        }
        asm volatile("cp.async.commit_group;" ::: "memory");
    };

    issue(0, 0); issue(1, 32); issue(2, 64);

    const int arow = wm * 64 + (lane & 15);
    const int aoff = arow * PITCH + ((lane >> 4) << 4);
    const int brow = wn * 32 + (lane & 7);
    const int boff = brow * PITCH + (((lane >> 3) & 1) << 4);

    for (int c = 0; c < 16; ++c) {
        asm volatile("cp.async.wait_group 2;" ::: "memory");
        __syncthreads();
        if (c + 3 < 16) issue((c + 3) & 3, (c + 3) << 5);
        uint32_t base = sb0 + (c & 3) * STG1;
#pragma unroll
        for (int ks = 0; ks < 2; ks++) {
            const int kb = ks * 32;
            uint32_t ah[4][4], bh[4][2];
#pragma unroll
            for (int mi = 0; mi < 4; mi++)
                ldm_x4(ah[mi][0], ah[mi][1], ah[mi][2], ah[mi][3],
                       base + aoff + mi * (16 * PITCH) + kb);
#pragma unroll
            for (int ni = 0; ni < 4; ni++)
                ldm_x2(bh[ni][0], bh[ni][1],
                       base + MATB + boff + ni * (8 * PITCH) + kb);
#pragma unroll
            for (int mi = 0; mi < 4; mi++)
#pragma unroll
                for (int ni = 0; ni < 4; ni++) {
                    float* cc = acc[mi][ni];
                    mma_bf16(cc[0], cc[1], cc[2], cc[3],
                             ah[mi][0], ah[mi][1], ah[mi][2], ah[mi][3],
                             bh[ni][0], bh[ni][1]);
                }
        }
    }

#pragma unroll
    for (int mi = 0; mi < 4; mi++) {
        int r = m0 + wm * 64 + mi * 16 + (lane >> 2);
#pragma unroll
        for (int ni = 0; ni < 4; ni++) {
            int n = n0 + wn * 32 + ni * 8 + ((lane & 3) << 1);
            float v0 = vec[n], v1 = vec[n + 1];
            float* cc = acc[mi][ni];
            float2 o0 = {alpha * cc[0] + vc * v0, alpha * cc[1] + vc * v1};
            float2 o1 = {alpha * cc[2] + vc * v0, alpha * cc[3] + vc * v1};
            *reinterpret_cast<float2*>(C + (size_t)r * ldc + n) = o0;
            *reinterpret_cast<float2*>(C + (size_t)(r + 8) * ldc + n) = o1;
        }
    }
}

// ---------------- RNN chunk: 128 steps, parallel producers, hoisted mapa ----------------
// dynamic smem (bytes):
//   [0, 4352)         h ping-pong [2][544]
//   [4352, 37120)     U slice     [128][64]
//   [37120, 69888)    g ring fp32 [128][64]
//   [69888, 86272)    qg ring bf16[128][64]
#define NSTEP 128
#define RNN_SMEM 86272
__global__ void __cluster_dims__(8, 1, 1) __launch_bounds__(256, 1)
rnn_chunk(const float* __restrict__ W_hh, const float* __restrict__ U,
          const float* __restrict__ hin, float* __restrict__ hout,
          float* __restrict__ g_out, __nv_bfloat16* __restrict__ qgh,
          int t0, float* __restrict__ h_lastp) {
    extern __shared__ char smraw[];
    float* h_sh = reinterpret_cast<float*>(smraw);
    float* U_s  = reinterpret_cast<float*>(smraw + 4352);
    float* g_s  = reinterpret_cast<float*>(smraw + 37120);
    __nv_bfloat16* q_s = reinterpret_cast<__nv_bfloat16*>(smraw + 69888);
    const int tid = threadIdx.x;
    const int r = tid >> 2, s = tid & 3;
    uint32_t rank; asm("mov.u32 %0, %%cluster_ctarank;" : "=r"(rank));
    const int grow = (int)rank * 64 + r;
    const int gidx = ((grow >> 7) * 136) + (grow & 127);

    // preload U slice: 128 steps x 64 floats
    {
        const float* src = U + (size_t)t0 * 512 + rank * 64;
        const uint32_t udst = smem_u32(U_s);
#pragma unroll
        for (int i = 0; i < 8; i++) {
            int idx = tid + (i << 8);             // 0..2047
            int tl = idx >> 4, seg = idx & 15;
            cpa16(udst + (uint32_t)(tl * 256 + seg * 16),
                  src + (size_t)tl * 512 + seg * 4);
        }
        asm volatile("cp.async.commit_group;" ::: "memory");
    }

    ull w2[64];
    const float4* w4 = reinterpret_cast<const float4*>(W_hh + (size_t)grow * 512 + s * 128);
#pragma unroll
    for (int u = 0; u < 32; u++) {
        float4 v = w4[u];
        w2[2 * u]     = pack2(v.x, v.y);
        w2[2 * u + 1] = pack2(v.z, v.w);
    }
    for (int i = tid; i < 512; i += 256)
        h_sh[((i >> 7) * 136) + (i & 127)] = hin[i];
    asm volatile("cp.async.wait_group 0;" ::: "memory");
    __syncthreads();
    asm volatile("barrier.cluster.arrive.aligned;" ::: "memory");
    asm volatile("barrier.cluster.wait.aligned;" ::: "memory");

    // hoisted remote addresses: this thread broadcasts to CTAs (2s) and (2s+1)
    const uint32_t lb0 = smem_u32(&h_sh[gidx]);
    const uint32_t lb1 = smem_u32(&h_sh[544 + gidx]);
    uint32_t r00, r01, r10, r11;
    {
        uint32_t c0 = 2u * (uint32_t)s, c1 = c0 + 1u;
        asm("mapa.shared::cluster.u32 %0, %1, %2;" : "=r"(r00) : "r"(lb0), "r"(c0));
        asm("mapa.shared::cluster.u32 %0, %1, %2;" : "=r"(r01) : "r"(lb0), "r"(c1));
        asm("mapa.shared::cluster.u32 %0, %1, %2;" : "=r"(r10) : "r"(lb1), "r"(c0));
        asm("mapa.shared::cluster.u32 %0, %1, %2;" : "=r"(r11) : "r"(lb1), "r"(c1));
    }

    float hlast = 0.f;
    for (int tl = 0; tl < NSTEP; tl++) {
        const int cur = tl & 1;
        float uval = U_s[tl * 64 + r];            // issued early, broadcast across 4 lanes
        const ulonglong2* h4 = reinterpret_cast<const ulonglong2*>(&h_sh[cur * 544 + s * 136]);
        ull a0 = 0ULL, a1 = 0ULL, a2 = 0ULL, a3 = 0ULL;
#pragma unroll
        for (int u = 0; u < 32; u += 2) {
            ulonglong2 p = h4[u];
            ulonglong2 q = h4[u + 1];
            ffma2(a0, w2[2 * u],     p.x);
            ffma2(a1, w2[2 * u + 1], p.y);
            ffma2(a2, w2[2 * u + 2], q.x);
            ffma2(a3, w2[2 * u + 3], q.y);
        }
        float e, f, g2, h2v, i2, j2, k2, l2;
        unpack2(e, f, a0); unpack2(g2, h2v, a1);
        unpack2(i2, j2, a2); unpack2(k2, l2, a3);
        float sum = ((e + f) + (g2 + h2v)) + ((i2 + j2) + (k2 + l2));
        sum += __shfl_xor_sync(0xffffffffu, sum, 1);
        sum += __shfl_xor_sync(0xffffffffu, sum, 2);
        float hn = tanhf(uval + sum);             // all 4 sibling lanes (identical)
        if (s == 0) g_s[tl * 64 + r] = hn;
        if (s == 1) q_s[tl * 64 + r] = __float2bfloat16(hn);
        if (tl == NSTEP - 1) {
            hlast = hn;
        } else {
            uint32_t t0a = cur ? r10 : r00;       // wait: next buffer = cur^1
            uint32_t t1a = cur ? r11 : r01;
            if (cur) { t0a = r00; t1a = r01; } else { t0a = r10; t1a = r11; }
            asm volatile("st.shared::cluster.f32 [%0], %1;" :: "r"(t0a), "f"(hn));
            asm volatile("st.shared::cluster.f32 [%0], %1;" :: "r"(t1a), "f"(hn));
        }
        asm volatile("barrier.cluster.arrive.aligned;" ::: "memory");
        asm volatile("barrier.cluster.wait.aligned;" ::: "memory");
    }

    // bulk dump rings
    {
        const size_t gbase = (size_t)t0 * 512 + rank * 64;
        const float4* gsv = reinterpret_cast<const float4*>(g_s);
#pragma unroll
        for (int i = 0; i < 8; i++) {
            int idx = tid + (i << 8);             // 0..2047
            int tl = idx >> 4, c4 = idx & 15;
            *reinterpret_cast<float4*>(g_out + gbase + (size_t)tl * 512 + c4 * 4) =
                gsv[tl * 16 + c4];
        }
        const uint4* qsv = reinterpret_cast<const uint4*>(q_s);
#pragma unroll
        for (int i = 0; i < 4; i++) {
            int idx = tid + (i << 8);             // 0..1023
            int tl = idx >> 3, seg = idx & 7;
            *reinterpret_cast<uint4*>(
                reinterpret_cast<char*>(qgh + gbase + (size_t)tl * 512) + seg * 16) =
                qsv[tl * 8 + seg];
        }
    }
    if (s == 0) {
        hout[grow] = hlast;
        if (t0 == T_ - NSTEP) h_lastp[grow] = hlast;
    }
}

// ---------------- gather with exact fp32 rescoring (row-chunkable) ----------------
#define DELTA 96.f
__global__ void __launch_bounds__(256, 1)
gather_ex(const float* __restrict__ L, const float* __restrict__ Q,
          const float* __restrict__ Kp, const float* __restrict__ nrm,
          const float* __restrict__ V, float* __restrict__ out, int row_base) {
    __shared__ float s_q[512];
    __shared__ int   s_idx[2048];
    __shared__ float s_e[2048];
    __shared__ float red[8];
    __shared__ float s_max, s_exm, s_den;
    __shared__ int   s_cnt;
    const int tid = threadIdx.x, wid = tid >> 5, lane = tid & 31;
    const int row = blockIdx.x + row_base;
    const float* Lr = L + (size_t)row * 32768;

    s_q[tid]       = Q[(size_t)row * 512 + tid];
    s_q[tid + 256] = Q[(size_t)row * 512 + tid + 256];
    if (tid == 0) { s_cnt = 0; s_den = 0.f; }

    float lm = -3.4e38f;
    const float4* L4 = reinterpret_cast<const float4*>(Lr);
#pragma unroll
    for (int i = 0; i < 32; i++) {
        float4 v = L4[tid + 256 * i];
        lm = fmaxf(fmaxf(lm, v.x), fmaxf(fmaxf(v.y, v.z), v.w));
    }
#pragma unroll
    for (int o = 16; o; o >>= 1) lm = fmaxf(lm, __shfl_xor_sync(0xffffffffu, lm, o));
    if (lane == 0) red[wid] = lm;
    __syncthreads();
    if (tid < 8) {
        float v = red[tid];
#pragma unroll
        for (int o = 4; o; o >>= 1) v = fmaxf(v, __shfl_xor_sync(0xffu, v, o));
        if (tid == 0) s_max = v;
    }
    __syncthreads();
    const float thr = s_max - DELTA;

    for (int i = 0; i < 32; i++) {
        float4 v = L4[tid + 256 * i];
        int b4 = (tid + 256 * i) << 2;
        if (v.x > thr) { int sl = atomicAdd(&s_cnt, 1); if (sl < 2048) s_idx[sl] = b4; }
        if (v.y > thr) { int sl = atomicAdd(&s_cnt, 1); if (sl < 2048) s_idx[sl] = b4 + 1; }
        if (v.z > thr) { int sl = atomicAdd(&s_cnt, 1); if (sl < 2048) s_idx[sl] = b4 + 2; }
        if (v.w > thr) { int sl = atomicAdd(&s_cnt, 1); if (sl < 2048) s_idx[sl] = b4 + 3; }
    }
    __syncthreads();
    const int cnt = min(s_cnt, 2048);

    for (int j = wid; j < cnt; j += 8) {
        int idx = s_idx[j];
        const float* Kr = Kp + (size_t)idx * 1024;
        float d = 0.f;
#pragma unroll
        for (int i = 0; i < 16; i++) d += s_q[lane + 32 * i] * Kr[lane + 32 * i];
#pragma unroll
        for (int o = 16; o; o >>= 1) d += __shfl_xor_sync(0xffffffffu, d, o);
        if (lane == 0) s_e[j] = 16.f * d - 8.f * nrm[idx];
    }
    __syncthreads();

    float em = -3.4e38f;
    for (int j = tid; j < cnt; j += 256) em = fmaxf(em, s_e[j]);
#pragma unroll
    for (int o = 16; o; o >>= 1) em = fmaxf(em, __shfl_xor_sync(0xffffffffu, em, o));
    if (lane == 0) red[wid] = em;
    __syncthreads();
    if (tid < 8) {
        float v = red[tid];
#pragma unroll
        for (int o = 4; o; o >>= 1) v = fmaxf(v, __shfl_xor_sync(0xffu, v, o));
        if (tid == 0) s_exm = v;
    }
    __syncthreads();
    const float exm = s_exm;
    float den = 0.f;
    for (int j = tid; j < cnt; j += 256) {
        float e = s_e[j];
        float p = (e > exm - 25.f) ? expf(e - exm) : 0.f;
        s_e[j] = p;
        den += p;
    }
#pragma unroll
    for (int o = 16; o; o >>= 1) den += __shfl_xor_sync(0xffffffffu, den, o);
    if (lane == 0 && den != 0.f) atomicAdd(&s_den, den);
    __syncthreads();

    float acc0 = 0.f, acc1 = 0.f;
    for (int j = 0; j < cnt; j++) {
        float p = s_e[j];
        if (p > 0.f) {
            const float* Vr = V + (size_t)s_idx[j] * 1024;
            acc0 += p * Vr[tid];
            acc1 += p * Vr[tid + 256];
        }
    }
    out[(size_t)row * 512 + tid]       = acc0 / s_den;
    out[(size_t)row * 512 + tid + 256] = acc1 / s_den;
}

// ---------------- launch ----------------
extern "C" void kernel_launch(void* const* d_in, const int* in_sizes, int n_in,
                              void* d_out, int out_size) {
    const float* inp   = (const float*)d_in[0];
    const float* x_obs = (const float*)d_in[1];
    const float* patt  = (const float*)d_in[2];
    const float* h0    = (const float*)d_in[3];
    const float* W_ih  = (const float*)d_in[4];
    const float* W_hh  = (const float*)d_in[5];
    const float* b_ih  = (const float*)d_in[6];
    const float* b_hh  = (const float*)d_in[7];

    float* out     = (float*)d_out;
    float* prob_g  = out;
    float* prob_x  = out + 1024 * 512;
    float* g_cur   = out + 2 * 1024 * 512;
    float* h_lastp = out + 3 * 1024 * 512;

    float *U, *Lx, *Lg, *nx, *ng, *bs, *hst;
    __nv_bfloat16 *xvh, *gkh, *qxh, *qgh;
    cudaGetSymbolAddress((void**)&U,  d_U);
    cudaGetSymbolAddress((void**)&Lx, d_Lx);
    cudaGetSymbolAddress((void**)&Lg, d_Lg);
    cudaGetSymbolAddress((void**)&nx, d_nx);
    cudaGetSymbolAddress((void**)&ng, d_ng);
    cudaGetSymbolAddress((void**)&bs, d_bsum);
    cudaGetSymbolAddress((void**)&hst, d_hstate);
    cudaGetSymbolAddress((void**)&xvh, d_xv_hi);
    cudaGetSymbolAddress((void**)&gkh, d_gk_hi);
    cudaGetSymbolAddress((void**)&qxh, d_qx_hi);
    cudaGetSymbolAddress((void**)&qgh, d_qg_hi);

    const int smemGemm = 2 * 2 * 128 * PADK * 4;   // 73728
    const int smem1p   = 4 * STG1;                 // 81920

    static int inited = 0;
    static cudaStream_t s1, s2;
    static cudaEvent_t evFork, evPrep, evX, evG;
    static cudaEvent_t evR[8];
    if (!inited) {
        cudaFuncSetAttribute(gemm_nt, cudaFuncAttributeMaxDynamicSharedMemorySize, smemGemm);
        cudaFuncSetAttribute(gemm1p, cudaFuncAttributeMaxDynamicSharedMemorySize, smem1p);
        cudaFuncSetAttribute(rnn_chunk, cudaFuncAttributeMaxDynamicSharedMemorySize, RNN_SMEM);
        cudaStreamCreateWithFlags(&s1, cudaStreamNonBlocking);
        cudaStreamCreateWithFlags(&s2, cudaStreamNonBlocking);
        cudaEventCreateWithFlags(&evFork, cudaEventDisableTiming);
        cudaEventCreateWithFlags(&evPrep, cudaEventDisableTiming);
        cudaEventCreateWithFlags(&evX, cudaEventDisableTiming);
        cudaEventCreateWithFlags(&evG, cudaEventDisableTiming);
        for (int i = 0; i < 8; i++) cudaEventCreateWithFlags(&evR[i], cudaEventDisableTiming);
        inited = 1;
    }

    cudaEventRecord(evFork, 0);
    cudaStreamWaitEvent(s1, evFork, 0);
    cudaStreamWaitEvent(s2, evFork, 0);

    // ---- s1: x-retrieval chain ----
    prep_patterns<<<M_, 256, 0, s1>>>(patt, xvh, gkh, nx, ng);
    cudaEventRecord(evPrep, s1);
    split_q<<<1024, 128, 0, s1>>>(x_obs, qxh);
    gemm1p<<<2048, 256, smem1p, s1>>>(qxh, xvh, nx, 16.f, -8.f, Lx, 32768, 8, 0);
    gather_ex<<<1024, 256, 0, s1>>>(Lx, x_obs, patt, nx, patt, prob_x, 0);
    cudaEventRecord(evX, s1);

    // ---- main: U -> 8 RNN chunks ----
    bsum_kernel<<<1, 512>>>(b_ih, b_hh, bs);
    gemm_nt<<<dim3(8, 4), 256, smemGemm>>>(inp, 128, W_ih, 128, bs, 1.f, 1.f, U, 512, 128);
    for (int c = 0; c < 8; c++) {
        rnn_chunk<<<8, 256, RNN_SMEM>>>(W_hh, U, (c == 0) ? h0 : hst, hst,
                                        g_cur, qgh, NSTEP * c, h_lastp);
        cudaEventRecord(evR[c], 0);
    }

    // ---- s2: g-retrieval pipelined over RNN chunks ----
    cudaStreamWaitEvent(s2, evPrep, 0);
    for (int c = 0; c < 8; c++) {
        cudaStreamWaitEvent(s2, evR[c], 0);
        gemm1p<<<256, 256, smem1p, s2>>>(qgh, gkh, ng, 16.f, -8.f, Lg, 32768, 1, c);
        gather_ex<<<128, 256, 0, s2>>>(Lg, g_cur, patt + 512, ng, patt, prob_g, NSTEP * c);
    }
    cudaEventRecord(evG, s2);

    cudaStreamWaitEvent(0, evX, 0);
    cudaStreamWaitEvent(0, evG, 0);
}

// round 15
// speedup vs baseline: 1.0392x; 1.0392x over previous
#include <cuda_runtime.h>
#include <cuda_bf16.h>
#include <cstdint>

typedef unsigned long long ull;

#define T_ 1024
#define I_ 128
#define H_ 512
#define O_ 512
#define M_ 32768

// ---------------- device scratch ----------------
__device__ float d_U[T_ * H_];
__device__ float d_Lx[(size_t)M_ * T_];
__device__ float d_Lg[(size_t)M_ * T_];
__device__ float d_nx[M_];
__device__ float d_ng[M_];
__device__ float d_bsum[H_];
__device__ float d_hstate[H_];
__device__ __nv_bfloat16 d_xv_hi[(size_t)M_ * 512];
__device__ __nv_bfloat16 d_gk_hi[(size_t)M_ * 512];
__device__ __nv_bfloat16 d_qx_hi[(size_t)T_ * 512];
__device__ __nv_bfloat16 d_qg_hi[(size_t)T_ * 512];

// ---------------- helpers ----------------
__device__ __forceinline__ uint32_t smem_u32(const void* p) {
    uint32_t a;
    asm("{ .reg .u64 t; cvta.to.shared.u64 t, %1; cvt.u32.u64 %0, t; }" : "=r"(a) : "l"(p));
    return a;
}
__device__ __forceinline__ void ffma2(ull& d, ull a, ull b) {
    asm("fma.rn.f32x2 %0, %1, %2, %0;" : "+l"(d) : "l"(a), "l"(b));
}
__device__ __forceinline__ ull pack2(float x, float y) {
    ull r; asm("mov.b64 %0, {%1,%2};" : "=l"(r) : "f"(x), "f"(y)); return r;
}
__device__ __forceinline__ void unpack2(float& lo, float& hi, ull v) {
    asm("mov.b64 {%0,%1}, %2;" : "=f"(lo), "=f"(hi) : "l"(v));
}
__device__ __forceinline__ void cpa16(uint32_t s, const void* g) {
    asm volatile("cp.async.cg.shared.global [%0], [%1], 16;" :: "r"(s), "l"(g));
}
__device__ __forceinline__ void ldm_x4(uint32_t& r0, uint32_t& r1, uint32_t& r2, uint32_t& r3,
                                       uint32_t addr) {
    asm volatile("ldmatrix.sync.aligned.m8n8.x4.shared.b16 {%0,%1,%2,%3}, [%4];"
                 : "=r"(r0), "=r"(r1), "=r"(r2), "=r"(r3) : "r"(addr));
}
__device__ __forceinline__ void ldm_x2(uint32_t& r0, uint32_t& r1, uint32_t addr) {
    asm volatile("ldmatrix.sync.aligned.m8n8.x2.shared.b16 {%0,%1}, [%2];"
                 : "=r"(r0), "=r"(r1) : "r"(addr));
}
__device__ __forceinline__ void mma_bf16(float& c0, float& c1, float& c2, float& c3,
                                         uint32_t a0, uint32_t a1, uint32_t a2, uint32_t a3,
                                         uint32_t b0, uint32_t b1) {
    asm volatile(
        "mma.sync.aligned.m16n8k16.row.col.f32.bf16.bf16.f32 "
        "{%0,%1,%2,%3}, {%4,%5,%6,%7}, {%8,%9}, {%0,%1,%2,%3};"
        : "+f"(c0), "+f"(c1), "+f"(c2), "+f"(c3)
        : "r"(a0), "r"(a1), "r"(a2), "r"(a3), "r"(b0), "r"(b1));
}

// ---------------- prologue ----------------
__global__ void bsum_kernel(const float* __restrict__ a, const float* __restrict__ b,
                            float* __restrict__ o) {
    int i = threadIdx.x; o[i] = a[i] + b[i];
}

__global__ void prep_patterns(const float* __restrict__ P,
                              __nv_bfloat16* __restrict__ xh, __nv_bfloat16* __restrict__ gh,
                              float* __restrict__ nx, float* __restrict__ ng) {
    __shared__ float s_nx, s_ng;
    int row = blockIdx.x;
    int c = threadIdx.x;
    if (c == 0) { s_nx = 0.f; s_ng = 0.f; }
    __syncthreads();
    float4 v = reinterpret_cast<const float4*>(P + (size_t)row * 1024)[c];
    float f[4] = {v.x, v.y, v.z, v.w};
    float sq = f[0] * f[0] + f[1] * f[1] + f[2] * f[2] + f[3] * f[3];
    __nv_bfloat16 h[4];
#pragma unroll
    for (int j = 0; j < 4; j++) h[j] = __float2bfloat16(f[j]);
    int col = c * 4;
    __nv_bfloat16* dh; size_t off;
    if (col < 512) { dh = xh; off = (size_t)row * 512 + col; }
    else           { dh = gh; off = (size_t)row * 512 + col - 512; }
    reinterpret_cast<__nv_bfloat162*>(dh + off)[0] = __nv_bfloat162(h[0], h[1]);
    reinterpret_cast<__nv_bfloat162*>(dh + off)[1] = __nv_bfloat162(h[2], h[3]);
#pragma unroll
    for (int o = 16; o; o >>= 1) sq += __shfl_xor_sync(0xffffffffu, sq, o);
    if ((threadIdx.x & 31) == 0) {
        if (col < 512) atomicAdd(&s_nx, sq); else atomicAdd(&s_ng, sq);
    }
    __syncthreads();
    if (c == 0) { nx[row] = s_nx; ng[row] = s_ng; }
}

__global__ void split_q(const float* __restrict__ X, __nv_bfloat16* __restrict__ hi) {
    int row = blockIdx.x;
    int c = threadIdx.x;
    float4 v = reinterpret_cast<const float4*>(X + (size_t)row * 512)[c];
    __nv_bfloat16 h[4] = {__float2bfloat16(v.x), __float2bfloat16(v.y),
                          __float2bfloat16(v.z), __float2bfloat16(v.w)};
    size_t off = (size_t)row * 512 + c * 4;
    reinterpret_cast<__nv_bfloat162*>(hi + off)[0] = __nv_bfloat162(h[0], h[1]);
    reinterpret_cast<__nv_bfloat162*>(hi + off)[1] = __nv_bfloat162(h[2], h[3]);
}

// ---------------- fp32 f32x2 GEMM (U precompute, K=128) ----------------
#define PADK 36
__global__ void __launch_bounds__(256, 1)
gemm_nt(const float* __restrict__ A, int lda,
        const float* __restrict__ B, int ldb,
        const float* __restrict__ vec, float alpha, float vc,
        float* __restrict__ C, int ldc, int K) {
    extern __shared__ float smf[];
    float* AsBase = smf;
    float* BsBase = smf + 2 * 128 * PADK;
    const int tid = threadIdx.x;
    const int tx = tid & 15, ty = tid >> 4;
    const int m0 = blockIdx.x << 7, n0 = blockIdx.y << 7;
    const int lrow = tid >> 3, lq = tid & 7;
    const uint32_t sA = smem_u32(AsBase), sB = smem_u32(BsBase);

    ull acc[64];
#pragma unroll
    for (int i = 0; i < 64; i++) acc[i] = 0ULL;

    auto issue = [&](int buf, int k0) {
        uint32_t da = sA + (uint32_t)buf * (128 * PADK * 4);
        uint32_t db = sB + (uint32_t)buf * (128 * PADK * 4);
#pragma unroll
        for (int l = 0; l < 4; l++) {
            int row = lrow + (l << 5);
            uint32_t so = (((uint32_t)(row * PADK) + (uint32_t)(lq << 2)) << 2);
            cpa16(da + so, A + (size_t)(m0 + row) * lda + k0 + (lq << 2));
            cpa16(db + so, B + (size_t)(n0 + row) * ldb + k0 + (lq << 2));
        }
        asm volatile("cp.async.commit_group;" ::: "memory");
    };

    const int nch = K >> 5;
    issue(0, 0);
    asm volatile("cp.async.wait_group 0;" ::: "memory");
    __syncthreads();

    for (int c = 0; c < nch; ++c) {
        if (c + 1 < nch) issue((c + 1) & 1, (c + 1) << 5);
        const float* As = AsBase + (c & 1) * (128 * PADK);
        const float* Bs = BsBase + (c & 1) * (128 * PADK);
#pragma unroll
        for (int k2 = 0; k2 < 16; k2++) {
            const int k = k2 << 1;
            ull a2[8], b2[8];
#pragma unroll
            for (int i = 0; i < 8; i++)
                a2[i] = *reinterpret_cast<const ull*>(As + ((i << 4) + ty) * PADK + k);
#pragma unroll
            for (int j = 0; j < 8; j++)
                b2[j] = *reinterpret_cast<const ull*>(Bs + ((j << 4) + tx) * PADK + k);
#pragma unroll
            for (int i = 0; i < 8; i++)
#pragma unroll
                for (int j = 0; j < 8; j++)
                    ffma2(acc[(i << 3) + j], a2[i], b2[j]);
        }
        asm volatile("cp.async.wait_group 0;" ::: "memory");
        __syncthreads();
    }

#pragma unroll
    for (int i = 0; i < 8; i++) {
        int m = m0 + (i << 4) + ty;
#pragma unroll
        for (int j = 0; j < 8; j++) {
            int n = n0 + (j << 4) + tx;
            float lo, hi; unpack2(lo, hi, acc[(i << 3) + j]);
            C[(size_t)m * ldc + n] = alpha * (lo + hi) + vc * vec[n];
        }
    }
}

// ---------------- single-pass bf16 HMMA GEMM (chunkable in m) ----------------
#define PITCH 80
#define MATB  (128 * PITCH)
#define STG1  (2 * MATB)

__global__ void __launch_bounds__(256, 1)
gemm1p(const __nv_bfloat16* __restrict__ A, const __nv_bfloat16* __restrict__ B,
       const float* __restrict__ vec, float alpha, float vc,
       float* __restrict__ C, int ldc, int m_span, int m_base) {
    extern __shared__ char sm[];
    const uint32_t sb0 = smem_u32(sm);
    const int tid = threadIdx.x, wid = tid >> 5, lane = tid & 31;
    const int wm = wid >> 2, wn = wid & 3;
    const int gi = blockIdx.x;
    const int m0 = (m_base + (gi % m_span)) << 7, n0 = (gi / m_span) << 7;

    float acc[4][4][4];
#pragma unroll
    for (int i = 0; i < 4; i++)
#pragma unroll
        for (int j = 0; j < 4; j++)
#pragma unroll
            for (int k = 0; k < 4; k++) acc[i][j][k] = 0.f;

    auto issue = [&](int stage, int k0) {
        uint32_t base = sb0 + stage * STG1;
#pragma unroll
        for (int t = 0; t < 2; t++) {
            const __nv_bfloat16* G = t ? B : A;
            int r0 = t ? n0 : m0;
#pragma unroll
            for (int q = 0; q < 2; q++) {
                int idx = tid + (q << 8);
                int row = idx >> 2, seg = idx & 3;
                cpa16(base + t * MATB + row * PITCH + seg * 16,
                      G + (size_t)(r0 + row) * 512 + k0 + seg * 8);
            }
        }
        asm volatile("cp.async.commit_group;" ::: "memory");
    };

    issue(0, 0); issue(1, 32); issue(2, 64);

    const int arow = wm * 64 + (lane & 15);
    const int aoff = arow * PITCH + ((lane >> 4) << 4);
    const int brow = wn * 32 + (lane & 7);
    const int boff = brow * PITCH + (((lane >> 3) & 1) << 4);

    for (int c = 0; c < 16; ++c) {
        asm volatile("cp.async.wait_group 2;" ::: "memory");
        __syncthreads();
        if (c + 3 < 16) issue((c + 3) & 3, (c + 3) << 5);
        uint32_t base = sb0 + (c & 3) * STG1;
#pragma unroll
        for (int ks = 0; ks < 2; ks++) {
            const int kb = ks * 32;
            uint32_t ah[4][4], bh[4][2];
#pragma unroll
            for (int mi = 0; mi < 4; mi++)
                ldm_x4(ah[mi][0], ah[mi][1], ah[mi][2], ah[mi][3],
                       base + aoff + mi * (16 * PITCH) + kb);
#pragma unroll
            for (int ni = 0; ni < 4; ni++)
                ldm_x2(bh[ni][0], bh[ni][1],
                       base + MATB + boff + ni * (8 * PITCH) + kb);
#pragma unroll
            for (int mi = 0; mi < 4; mi++)
#pragma unroll
                for (int ni = 0; ni < 4; ni++) {
                    float* cc = acc[mi][ni];
                    mma_bf16(cc[0], cc[1], cc[2], cc[3],
                             ah[mi][0], ah[mi][1], ah[mi][2], ah[mi][3],
                             bh[ni][0], bh[ni][1]);
                }
        }
    }

#pragma unroll
    for (int mi = 0; mi < 4; mi++) {
        int r = m0 + wm * 64 + mi * 16 + (lane >> 2);
#pragma unroll
        for (int ni = 0; ni < 4; ni++) {
            int n = n0 + wn * 32 + ni * 8 + ((lane & 3) << 1);
            float v0 = vec[n], v1 = vec[n + 1];
            float* cc = acc[mi][ni];
            float2 o0 = {alpha * cc[0] + vc * v0, alpha * cc[1] + vc * v1};
            float2 o1 = {alpha * cc[2] + vc * v0, alpha * cc[3] + vc * v1};
            *reinterpret_cast<float2*>(C + (size_t)r * ldc + n) = o0;
            *reinterpret_cast<float2*>(C + (size_t)(r + 8) * ldc + n) = o1;
        }
    }
}

// ---------------- RNN chunk: split arrive/wait, spread producers, 256 steps ----------------
// dynamic smem (bytes):
//   [0, 4352)          h ping-pong  [2][544]
//   [4352, 69888)      U slice      [256][64]
//   [69888, 135424)    g ring fp32  [256][64]
//   [135424, 168192)   qg ring bf16 [256][64]
#define NSTEP 256
#define RNN_SMEM 168192
__global__ void __cluster_dims__(8, 1, 1) __launch_bounds__(256, 1)
rnn_chunk(const float* __restrict__ W_hh, const float* __restrict__ U,
          const float* __restrict__ hin, float* __restrict__ hout,
          float* __restrict__ g_out, __nv_bfloat16* __restrict__ qgh,
          int t0, float* __restrict__ h_lastp) {
    extern __shared__ char smraw[];
    float* h_sh = reinterpret_cast<float*>(smraw);
    float* U_s  = reinterpret_cast<float*>(smraw + 4352);
    float* g_s  = reinterpret_cast<float*>(smraw + 69888);
    __nv_bfloat16* q_s = reinterpret_cast<__nv_bfloat16*>(smraw + 135424);
    const int tid = threadIdx.x;
    const int r = tid >> 2, s = tid & 3;
    uint32_t rank; asm("mov.u32 %0, %%cluster_ctarank;" : "=r"(rank));
    const int grow = (int)rank * 64 + r;
    const int gidx = ((grow >> 7) * 136) + (grow & 127);

    // preload U slice: 256 steps x 64 floats
    {
        const float* src = U + (size_t)t0 * 512 + rank * 64;
        const uint32_t udst = smem_u32(U_s);
#pragma unroll
        for (int i = 0; i < 16; i++) {
            int idx = tid + (i << 8);             // 0..4095
            int tl = idx >> 4, seg = idx & 15;
            cpa16(udst + (uint32_t)(tl * 256 + seg * 16),
                  src + (size_t)tl * 512 + seg * 4);
        }
        asm volatile("cp.async.commit_group;" ::: "memory");
    }

    ull w2[64];
    const float4* w4 = reinterpret_cast<const float4*>(W_hh + (size_t)grow * 512 + s * 128);
#pragma unroll
    for (int u = 0; u < 32; u++) {
        float4 v = w4[u];
        w2[2 * u]     = pack2(v.x, v.y);
        w2[2 * u + 1] = pack2(v.z, v.w);
    }
    for (int i = tid; i < 512; i += 256)
        h_sh[((i >> 7) * 136) + (i & 127)] = hin[i];
    asm volatile("cp.async.wait_group 0;" ::: "memory");
    __syncthreads();
    asm volatile("barrier.cluster.arrive.aligned;" ::: "memory");
    asm volatile("barrier.cluster.wait.aligned;" ::: "memory");

    // hoisted remote addresses: this thread broadcasts to CTAs 2s and 2s+1
    const uint32_t lb0 = smem_u32(&h_sh[gidx]);          // buffer 0 slot
    const uint32_t lb1 = smem_u32(&h_sh[544 + gidx]);    // buffer 1 slot
    uint32_t r00, r01, r10, r11;
    {
        uint32_t c0 = 2u * (uint32_t)s, c1 = c0 + 1u;
        asm("mapa.shared::cluster.u32 %0, %1, %2;" : "=r"(r00) : "r"(lb0), "r"(c0));
        asm("mapa.shared::cluster.u32 %0, %1, %2;" : "=r"(r01) : "r"(lb0), "r"(c1));
        asm("mapa.shared::cluster.u32 %0, %1, %2;" : "=r"(r10) : "r"(lb1), "r"(c0));
        asm("mapa.shared::cluster.u32 %0, %1, %2;" : "=r"(r11) : "r"(lb1), "r"(c1));
    }

    float uval = U_s[r];                          // step 0
    float hlast = 0.f;
    for (int tl = 0; tl < NSTEP; tl++) {
        const int cur = tl & 1;
        const ulonglong2* h4 = reinterpret_cast<const ulonglong2*>(&h_sh[cur * 544 + s * 136]);
        ull a0 = 0ULL, a1 = 0ULL, a2 = 0ULL, a3 = 0ULL;
#pragma unroll
        for (int u = 0; u < 32; u += 2) {
            ulonglong2 p = h4[u];
            ulonglong2 q = h4[u + 1];
            ffma2(a0, w2[2 * u],     p.x);
            ffma2(a1, w2[2 * u + 1], p.y);
            ffma2(a2, w2[2 * u + 2], q.x);
            ffma2(a3, w2[2 * u + 3], q.y);
        }
        float e, f, g2, h2v, i2, j2, k2, l2;
        unpack2(e, f, a0); unpack2(g2, h2v, a1);
        unpack2(i2, j2, a2); unpack2(k2, l2, a3);
        float sum = ((e + f) + (g2 + h2v)) + ((i2 + j2) + (k2 + l2));
        sum += __shfl_xor_sync(0xffffffffu, sum, 1);
        sum += __shfl_xor_sync(0xffffffffu, sum, 2);
        float hn = tanhf(uval + sum);             // all 4 sibling lanes (identical)
        if (tl == NSTEP - 1) {
            hlast = hn;
            if (s == 0) g_s[tl * 64 + r] = hn;
            if (s == 1) q_s[tl * 64 + r] = __float2bfloat16(hn);
            break;                                 // no broadcast/barrier needed
        }
        // remote stores into NEXT buffer, then early arrive (release covers stores)
        uint32_t t0a = cur ? r00 : r10;
        uint32_t t1a = cur ? r01 : r11;
        asm volatile("st.shared::cluster.f32 [%0], %1;" :: "r"(t0a), "f"(hn));
        asm volatile("st.shared::cluster.f32 [%0], %1;" :: "r"(t1a), "f"(hn));
        asm volatile("barrier.cluster.arrive.aligned;" ::: "memory");
        // housekeeping hidden under the barrier drain
        if (s == 0) g_s[tl * 64 + r] = hn;
        if (s == 1) q_s[tl * 64 + r] = __float2bfloat16(hn);
        uval = U_s[(tl + 1) * 64 + r];
        asm volatile("barrier.cluster.wait.aligned;" ::: "memory");
    }

    __syncthreads();                               // g_s/q_s visible for dump
    // bulk dump g (fp32) and qg (bf16) rings to global
    {
        const size_t gbase = (size_t)t0 * 512 + rank * 64;
        const float4* gsv = reinterpret_cast<const float4*>(g_s);
#pragma unroll
        for (int i = 0; i < 16; i++) {
            int idx = tid + (i << 8);             // 0..4095
            int tl = idx >> 4, c4 = idx & 15;
            *reinterpret_cast<float4*>(g_out + gbase + (size_t)tl * 512 + c4 * 4) =
                gsv[tl * 16 + c4];
        }
        const uint4* qsv = reinterpret_cast<const uint4*>(q_s);
#pragma unroll
        for (int i = 0; i < 8; i++) {
            int idx = tid + (i << 8);             // 0..2047
            int tl = idx >> 3, seg = idx & 7;
            *reinterpret_cast<uint4*>(
                reinterpret_cast<char*>(qgh + gbase + (size_t)tl * 512) + seg * 16) =
                qsv[tl * 8 + seg];
        }
    }
    if (s == 0) {
        hout[grow] = hlast;
        if (t0 == T_ - NSTEP) h_lastp[grow] = hlast;
    }
}

// ---------------- gather with exact fp32 rescoring (row-chunkable) ----------------
#define DELTA 96.f
__global__ void __launch_bounds__(256, 1)
gather_ex(const float* __restrict__ L, const float* __restrict__ Q,
          const float* __restrict__ Kp, const float* __restrict__ nrm,
          const float* __restrict__ V, float* __restrict__ out, int row_base) {
    __shared__ float s_q[512];
    __shared__ int   s_idx[2048];
    __shared__ float s_e[2048];
    __shared__ float red[8];
    __shared__ float s_max, s_exm, s_den;
    __shared__ int   s_cnt;
    const int tid = threadIdx.x, wid = tid >> 5, lane = tid & 31;
    const int row = blockIdx.x + row_base;
    const float* Lr = L + (size_t)row * 32768;

    s_q[tid]       = Q[(size_t)row * 512 + tid];
    s_q[tid + 256] = Q[(size_t)row * 512 + tid + 256];
    if (tid == 0) { s_cnt = 0; s_den = 0.f; }

    float lm = -3.4e38f;
    const float4* L4 = reinterpret_cast<const float4*>(Lr);
#pragma unroll
    for (int i = 0; i < 32; i++) {
        float4 v = L4[tid + 256 * i];
        lm = fmaxf(fmaxf(lm, v.x), fmaxf(fmaxf(v.y, v.z), v.w));
    }
#pragma unroll
    for (int o = 16; o; o >>= 1) lm = fmaxf(lm, __shfl_xor_sync(0xffffffffu, lm, o));
    if (lane == 0) red[wid] = lm;
    __syncthreads();
    if (tid < 8) {
        float v = red[tid];
#pragma unroll
        for (int o = 4; o; o >>= 1) v = fmaxf(v, __shfl_xor_sync(0xffu, v, o));
        if (tid == 0) s_max = v;
    }
    __syncthreads();
    const float thr = s_max - DELTA;

    for (int i = 0; i < 32; i++) {
        float4 v = L4[tid + 256 * i];
        int b4 = (tid + 256 * i) << 2;
        if (v.x > thr) { int sl = atomicAdd(&s_cnt, 1); if (sl < 2048) s_idx[sl] = b4; }
        if (v.y > thr) { int sl = atomicAdd(&s_cnt, 1); if (sl < 2048) s_idx[sl] = b4 + 1; }
        if (v.z > thr) { int sl = atomicAdd(&s_cnt, 1); if (sl < 2048) s_idx[sl] = b4 + 2; }
        if (v.w > thr) { int sl = atomicAdd(&s_cnt, 1); if (sl < 2048) s_idx[sl] = b4 + 3; }
    }
    __syncthreads();
    const int cnt = min(s_cnt, 2048);

    for (int j = wid; j < cnt; j += 8) {
        int idx = s_idx[j];
        const float* Kr = Kp + (size_t)idx * 1024;
        float d = 0.f;
#pragma unroll
        for (int i = 0; i < 16; i++) d += s_q[lane + 32 * i] * Kr[lane + 32 * i];
#pragma unroll
        for (int o = 16; o; o >>= 1) d += __shfl_xor_sync(0xffffffffu, d, o);
        if (lane == 0) s_e[j] = 16.f * d - 8.f * nrm[idx];
    }
    __syncthreads();

    float em = -3.4e38f;
    for (int j = tid; j < cnt; j += 256) em = fmaxf(em, s_e[j]);
#pragma unroll
    for (int o = 16; o; o >>= 1) em = fmaxf(em, __shfl_xor_sync(0xffffffffu, em, o));
    if (lane == 0) red[wid] = em;
    __syncthreads();
    if (tid < 8) {
        float v = red[tid];
#pragma unroll
        for (int o = 4; o; o >>= 1) v = fmaxf(v, __shfl_xor_sync(0xffu, v, o));
        if (tid == 0) s_exm = v;
    }
    __syncthreads();
    const float exm = s_exm;
    float den = 0.f;
    for (int j = tid; j < cnt; j += 256) {
        float e = s_e[j];
        float p = (e > exm - 25.f) ? expf(e - exm) : 0.f;
        s_e[j] = p;
        den += p;
    }
#pragma unroll
    for (int o = 16; o; o >>= 1) den += __shfl_xor_sync(0xffffffffu, den, o);
    if (lane == 0 && den != 0.f) atomicAdd(&s_den, den);
    __syncthreads();

    float acc0 = 0.f, acc1 = 0.f;
    for (int j = 0; j < cnt; j++) {
        float p = s_e[j];
        if (p > 0.f) {
            const float* Vr = V + (size_t)s_idx[j] * 1024;
            acc0 += p * Vr[tid];
            acc1 += p * Vr[tid + 256];
        }
    }
    out[(size_t)row * 512 + tid]       = acc0 / s_den;
    out[(size_t)row * 512 + tid + 256] = acc1 / s_den;
}

// ---------------- launch: RNN chain enqueued first for dispatch priority ----------------
extern "C" void kernel_launch(void* const* d_in, const int* in_sizes, int n_in,
                              void* d_out, int out_size) {
    const float* inp   = (const float*)d_in[0];
    const float* x_obs = (const float*)d_in[1];
    const float* patt  = (const float*)d_in[2];
    const float* h0    = (const float*)d_in[3];
    const float* W_ih  = (const float*)d_in[4];
    const float* W_hh  = (const float*)d_in[5];
    const float* b_ih  = (const float*)d_in[6];
    const float* b_hh  = (const float*)d_in[7];

    float* out     = (float*)d_out;
    float* prob_g  = out;
    float* prob_x  = out + 1024 * 512;
    float* g_cur   = out + 2 * 1024 * 512;
    float* h_lastp = out + 3 * 1024 * 512;

    float *U, *Lx, *Lg, *nx, *ng, *bs, *hst;
    __nv_bfloat16 *xvh, *gkh, *qxh, *qgh;
    cudaGetSymbolAddress((void**)&U,  d_U);
    cudaGetSymbolAddress((void**)&Lx, d_Lx);
    cudaGetSymbolAddress((void**)&Lg, d_Lg);
    cudaGetSymbolAddress((void**)&nx, d_nx);
    cudaGetSymbolAddress((void**)&ng, d_ng);
    cudaGetSymbolAddress((void**)&bs, d_bsum);
    cudaGetSymbolAddress((void**)&hst, d_hstate);
    cudaGetSymbolAddress((void**)&xvh, d_xv_hi);
    cudaGetSymbolAddress((void**)&gkh, d_gk_hi);
    cudaGetSymbolAddress((void**)&qxh, d_qx_hi);
    cudaGetSymbolAddress((void**)&qgh, d_qg_hi);

    const int smemGemm = 2 * 2 * 128 * PADK * 4;   // 73728
    const int smem1p   = 4 * STG1;                 // 81920

    static int inited = 0;
    static cudaStream_t s1, s2;
    static cudaEvent_t evFork, evPrep, evX, evG;
    static cudaEvent_t evR[4];
    if (!inited) {
        cudaFuncSetAttribute(gemm_nt, cudaFuncAttributeMaxDynamicSharedMemorySize, smemGemm);
        cudaFuncSetAttribute(gemm1p, cudaFuncAttributeMaxDynamicSharedMemorySize, smem1p);
        cudaFuncSetAttribute(rnn_chunk, cudaFuncAttributeMaxDynamicSharedMemorySize, RNN_SMEM);
        cudaStreamCreateWithFlags(&s1, cudaStreamNonBlocking);
        cudaStreamCreateWithFlags(&s2, cudaStreamNonBlocking);
        cudaEventCreateWithFlags(&evFork, cudaEventDisableTiming);
        cudaEventCreateWithFlags(&evPrep, cudaEventDisableTiming);
        cudaEventCreateWithFlags(&evX, cudaEventDisableTiming);
        cudaEventCreateWithFlags(&evG, cudaEventDisableTiming);
        for (int i = 0; i < 4; i++) cudaEventCreateWithFlags(&evR[i], cudaEventDisableTiming);
        inited = 1;
    }

    cudaEventRecord(evFork, 0);
    cudaStreamWaitEvent(s1, evFork, 0);
    cudaStreamWaitEvent(s2, evFork, 0);

    // ---- main: U -> 4 RNN chunks (enqueued FIRST: oldest grids get SMs first) ----
    bsum_kernel<<<1, 512>>>(b_ih, b_hh, bs);
    gemm_nt<<<dim3(8, 4), 256, smemGemm>>>(inp, 128, W_ih, 128, bs, 1.f, 1.f, U, 512, 128);
    for (int c = 0; c < 4; c++) {
        rnn_chunk<<<8, 256, RNN_SMEM>>>(W_hh, U, (c == 0) ? h0 : hst, hst,
                                        g_cur, qgh, NSTEP * c, h_lastp);
        cudaEventRecord(evR[c], 0);
    }

    // ---- s1: x-retrieval chain (fills SMs around the RNN) ----
    prep_patterns<<<M_, 256, 0, s1>>>(patt, xvh, gkh, nx, ng);
    cudaEventRecord(evPrep, s1);
    split_q<<<1024, 128, 0, s1>>>(x_obs, qxh);
    gemm1p<<<2048, 256, smem1p, s1>>>(qxh, xvh, nx, 16.f, -8.f, Lx, 32768, 8, 0);
    gather_ex<<<1024, 256, 0, s1>>>(Lx, x_obs, patt, nx, patt, prob_x, 0);
    cudaEventRecord(evX, s1);

    // ---- s2: g-retrieval pipelined over RNN chunks ----
    cudaStreamWaitEvent(s2, evPrep, 0);
    for (int c = 0; c < 4; c++) {
        cudaStreamWaitEvent(s2, evR[c], 0);
        gemm1p<<<512, 256, smem1p, s2>>>(qgh, gkh, ng, 16.f, -8.f, Lg, 32768, 2, 2 * c);
        gather_ex<<<256, 256, 0, s2>>>(Lg, g_cur, patt + 512, ng, patt, prob_g, NSTEP * c);
    }
    cudaEventRecord(evG, s2);

    cudaStreamWaitEvent(0, evX, 0);
    cudaStreamWaitEvent(0, evG, 0);
}

// round 16
// speedup vs baseline: 1.0458x; 1.0063x over previous
#include <cuda_runtime.h>
#include <cuda_bf16.h>
#include <cstdint>

typedef unsigned long long ull;

#define T_ 1024
#define I_ 128
#define H_ 512
#define O_ 512
#define M_ 32768

// ---------------- device scratch ----------------
__device__ float d_U[T_ * H_];
__device__ float d_Lx[(size_t)M_ * T_];
__device__ float d_Lg[(size_t)M_ * T_];
__device__ float d_nx[M_];
__device__ float d_ng[M_];
__device__ float d_bsum[H_];
__device__ float d_hstate[H_];
__device__ __nv_bfloat16 d_xv_hi[(size_t)M_ * 512];
__device__ __nv_bfloat16 d_gk_hi[(size_t)M_ * 512];
__device__ __nv_bfloat16 d_qx_hi[(size_t)T_ * 512];
__device__ __nv_bfloat16 d_qg_hi[(size_t)T_ * 512];

// ---------------- helpers ----------------
__device__ __forceinline__ uint32_t smem_u32(const void* p) {
    uint32_t a;
    asm("{ .reg .u64 t; cvta.to.shared.u64 t, %1; cvt.u32.u64 %0, t; }" : "=r"(a) : "l"(p));
    return a;
}
__device__ __forceinline__ void ffma2(ull& d, ull a, ull b) {
    asm("fma.rn.f32x2 %0, %1, %2, %0;" : "+l"(d) : "l"(a), "l"(b));
}
__device__ __forceinline__ ull pack2(float x, float y) {
    ull r; asm("mov.b64 %0, {%1,%2};" : "=l"(r) : "f"(x), "f"(y)); return r;
}
__device__ __forceinline__ void unpack2(float& lo, float& hi, ull v) {
    asm("mov.b64 {%0,%1}, %2;" : "=f"(lo), "=f"(hi) : "l"(v));
}
__device__ __forceinline__ void cpa16(uint32_t s, const void* g) {
    asm volatile("cp.async.cg.shared.global [%0], [%1], 16;" :: "r"(s), "l"(g));
}
__device__ __forceinline__ void ldm_x4(uint32_t& r0, uint32_t& r1, uint32_t& r2, uint32_t& r3,
                                       uint32_t addr) {
    asm volatile("ldmatrix.sync.aligned.m8n8.x4.shared.b16 {%0,%1,%2,%3}, [%4];"
                 : "=r"(r0), "=r"(r1), "=r"(r2), "=r"(r3) : "r"(addr));
}
__device__ __forceinline__ void ldm_x2(uint32_t& r0, uint32_t& r1, uint32_t addr) {
    asm volatile("ldmatrix.sync.aligned.m8n8.x2.shared.b16 {%0,%1}, [%2];"
                 : "=r"(r0), "=r"(r1) : "r"(addr));
}
__device__ __forceinline__ void mma_bf16(float& c0, float& c1, float& c2, float& c3,
                                         uint32_t a0, uint32_t a1, uint32_t a2, uint32_t a3,
                                         uint32_t b0, uint32_t b1) {
    asm volatile(
        "mma.sync.aligned.m16n8k16.row.col.f32.bf16.bf16.f32 "
        "{%0,%1,%2,%3}, {%4,%5,%6,%7}, {%8,%9}, {%0,%1,%2,%3};"
        : "+f"(c0), "+f"(c1), "+f"(c2), "+f"(c3)
        : "r"(a0), "r"(a1), "r"(a2), "r"(a3), "r"(b0), "r"(b1));
}

// ---------------- prologue ----------------
__global__ void bsum_kernel(const float* __restrict__ a, const float* __restrict__ b,
                            float* __restrict__ o) {
    int i = threadIdx.x; o[i] = a[i] + b[i];
}

__global__ void prep_patterns(const float* __restrict__ P,
                              __nv_bfloat16* __restrict__ xh, __nv_bfloat16* __restrict__ gh,
                              float* __restrict__ nx, float* __restrict__ ng) {
    __shared__ float s_nx, s_ng;
    int row = blockIdx.x;
    int c = threadIdx.x;
    if (c == 0) { s_nx = 0.f; s_ng = 0.f; }
    __syncthreads();
    float4 v = reinterpret_cast<const float4*>(P + (size_t)row * 1024)[c];
    float f[4] = {v.x, v.y, v.z, v.w};
    float sq = f[0] * f[0] + f[1] * f[1] + f[2] * f[2] + f[3] * f[3];
    __nv_bfloat16 h[4];
#pragma unroll
    for (int j = 0; j < 4; j++) h[j] = __float2bfloat16(f[j]);
    int col = c * 4;
    __nv_bfloat16* dh; size_t off;
    if (col < 512) { dh = xh; off = (size_t)row * 512 + col; }
    else           { dh = gh; off = (size_t)row * 512 + col - 512; }
    reinterpret_cast<__nv_bfloat162*>(dh + off)[0] = __nv_bfloat162(h[0], h[1]);
    reinterpret_cast<__nv_bfloat162*>(dh + off)[1] = __nv_bfloat162(h[2], h[3]);
#pragma unroll
    for (int o = 16; o; o >>= 1) sq += __shfl_xor_sync(0xffffffffu, sq, o);
    if ((threadIdx.x & 31) == 0) {
        if (col < 512) atomicAdd(&s_nx, sq); else atomicAdd(&s_ng, sq);
    }
    __syncthreads();
    if (c == 0) { nx[row] = s_nx; ng[row] = s_ng; }
}

__global__ void split_q(const float* __restrict__ X, __nv_bfloat16* __restrict__ hi) {
    int row = blockIdx.x;
    int c = threadIdx.x;
    float4 v = reinterpret_cast<const float4*>(X + (size_t)row * 512)[c];
    __nv_bfloat16 h[4] = {__float2bfloat16(v.x), __float2bfloat16(v.y),
                          __float2bfloat16(v.z), __float2bfloat16(v.w)};
    size_t off = (size_t)row * 512 + c * 4;
    reinterpret_cast<__nv_bfloat162*>(hi + off)[0] = __nv_bfloat162(h[0], h[1]);
    reinterpret_cast<__nv_bfloat162*>(hi + off)[1] = __nv_bfloat162(h[2], h[3]);
}

// ---------------- fp32 f32x2 GEMM (U precompute, K=128) ----------------
#define PADK 36
__global__ void __launch_bounds__(256, 1)
gemm_nt(const float* __restrict__ A, int lda,
        const float* __restrict__ B, int ldb,
        const float* __restrict__ vec, float alpha, float vc,
        float* __restrict__ C, int ldc, int K) {
    extern __shared__ float smf[];
    float* AsBase = smf;
    float* BsBase = smf + 2 * 128 * PADK;
    const int tid = threadIdx.x;
    const int tx = tid & 15, ty = tid >> 4;
    const int m0 = blockIdx.x << 7, n0 = blockIdx.y << 7;
    const int lrow = tid >> 3, lq = tid & 7;
    const uint32_t sA = smem_u32(AsBase), sB = smem_u32(BsBase);

    ull acc[64];
#pragma unroll
    for (int i = 0; i < 64; i++) acc[i] = 0ULL;

    auto issue = [&](int buf, int k0) {
        uint32_t da = sA + (uint32_t)buf * (128 * PADK * 4);
        uint32_t db = sB + (uint32_t)buf * (128 * PADK * 4);
#pragma unroll
        for (int l = 0; l < 4; l++) {
            int row = lrow + (l << 5);
            uint32_t so = (((uint32_t)(row * PADK) + (uint32_t)(lq << 2)) << 2);
            cpa16(da + so, A + (size_t)(m0 + row) * lda + k0 + (lq << 2));
            cpa16(db + so, B + (size_t)(n0 + row) * ldb + k0 + (lq << 2));
        }
        asm volatile("cp.async.commit_group;" ::: "memory");
    };

    const int nch = K >> 5;
    issue(0, 0);
    asm volatile("cp.async.wait_group 0;" ::: "memory");
    __syncthreads();

    for (int c = 0; c < nch; ++c) {
        if (c + 1 < nch) issue((c + 1) & 1, (c + 1) << 5);
        const float* As = AsBase + (c & 1) * (128 * PADK);
        const float* Bs = BsBase + (c & 1) * (128 * PADK);
#pragma unroll
        for (int k2 = 0; k2 < 16; k2++) {
            const int k = k2 << 1;
            ull a2[8], b2[8];
#pragma unroll
            for (int i = 0; i < 8; i++)
                a2[i] = *reinterpret_cast<const ull*>(As + ((i << 4) + ty) * PADK + k);
#pragma unroll
            for (int j = 0; j < 8; j++)
                b2[j] = *reinterpret_cast<const ull*>(Bs + ((j << 4) + tx) * PADK + k);
#pragma unroll
            for (int i = 0; i < 8; i++)
#pragma unroll
                for (int j = 0; j < 8; j++)
                    ffma2(acc[(i << 3) + j], a2[i], b2[j]);
        }
        asm volatile("cp.async.wait_group 0;" ::: "memory");
        __syncthreads();
    }

#pragma unroll
    for (int i = 0; i < 8; i++) {
        int m = m0 + (i << 4) + ty;
#pragma unroll
        for (int j = 0; j < 8; j++) {
            int n = n0 + (j << 4) + tx;
            float lo, hi; unpack2(lo, hi, acc[(i << 3) + j]);
            C[(size_t)m * ldc + n] = alpha * (lo + hi) + vc * vec[n];
        }
    }
}

// ---------------- single-pass bf16 HMMA GEMM (chunkable in m) ----------------
#define PITCH 80
#define MATB  (128 * PITCH)
#define STG1  (2 * MATB)

__global__ void __launch_bounds__(256, 1)
gemm1p(const __nv_bfloat16* __restrict__ A, const __nv_bfloat16* __restrict__ B,
       const float* __restrict__ vec, float alpha, float vc,
       float* __restrict__ C, int ldc, int m_span, int m_base) {
    extern __shared__ char sm[];
    const uint32_t sb0 = smem_u32(sm);
    const int tid = threadIdx.x, wid = tid >> 5, lane = tid & 31;
    const int wm = wid >> 2, wn = wid & 3;
    const int gi = blockIdx.x;
    const int m0 = (m_base + (gi % m_span)) << 7, n0 = (gi / m_span) << 7;

    float acc[4][4][4];
#pragma unroll
    for (int i = 0; i < 4; i++)
#pragma unroll
        for (int j = 0; j < 4; j++)
#pragma unroll
            for (int k = 0; k < 4; k++) acc[i][j][k] = 0.f;

    auto issue = [&](int stage, int k0) {
        uint32_t base = sb0 + stage * STG1;
#pragma unroll
        for (int t = 0; t < 2; t++) {
            const __nv_bfloat16* G = t ? B : A;
            int r0 = t ? n0 : m0;
#pragma unroll
            for (int q = 0; q < 2; q++) {
                int idx = tid + (q << 8);
                int row = idx >> 2, seg = idx & 3;
                cpa16(base + t * MATB + row * PITCH + seg * 16,
                      G + (size_t)(r0 + row) * 512 + k0 + seg * 8);
            }
        }
        asm volatile("cp.async.commit_group;" ::: "memory");
    };

    issue(0, 0); issue(1, 32); issue(2, 64);

    const int arow = wm * 64 + (lane & 15);
    const int aoff = arow * PITCH + ((lane >> 4) << 4);
    const int brow = wn * 32 + (lane & 7);
    const int boff = brow * PITCH + (((lane >> 3) & 1) << 4);

    for (int c = 0; c < 16; ++c) {
        asm volatile("cp.async.wait_group 2;" ::: "memory");
        __syncthreads();
        if (c + 3 < 16) issue((c + 3) & 3, (c + 3) << 5);
        uint32_t base = sb0 + (c & 3) * STG1;
#pragma unroll
        for (int ks = 0; ks < 2; ks++) {
            const int kb = ks * 32;
            uint32_t ah[4][4], bh[4][2];
#pragma unroll
            for (int mi = 0; mi < 4; mi++)
                ldm_x4(ah[mi][0], ah[mi][1], ah[mi][2], ah[mi][3],
                       base + aoff + mi * (16 * PITCH) + kb);
#pragma unroll
            for (int ni = 0; ni < 4; ni++)
                ldm_x2(bh[ni][0], bh[ni][1],
                       base + MATB + boff + ni * (8 * PITCH) + kb);
#pragma unroll
            for (int mi = 0; mi < 4; mi++)
#pragma unroll
                for (int ni = 0; ni < 4; ni++) {
                    float* cc = acc[mi][ni];
                    mma_bf16(cc[0], cc[1], cc[2], cc[3],
                             ah[mi][0], ah[mi][1], ah[mi][2], ah[mi][3],
                             bh[ni][0], bh[ni][1]);
                }
        }
    }

#pragma unroll
    for (int mi = 0; mi < 4; mi++) {
        int r = m0 + wm * 64 + mi * 16 + (lane >> 2);
#pragma unroll
        for (int ni = 0; ni < 4; ni++) {
            int n = n0 + wn * 32 + ni * 8 + ((lane & 3) << 1);
            float v0 = vec[n], v1 = vec[n + 1];
            float* cc = acc[mi][ni];
            float2 o0 = {alpha * cc[0] + vc * v0, alpha * cc[1] + vc * v1};
            float2 o1 = {alpha * cc[2] + vc * v0, alpha * cc[3] + vc * v1};
            *reinterpret_cast<float2*>(C + (size_t)r * ldc + n) = o0;
            *reinterpret_cast<float2*>(C + (size_t)(r + 8) * ldc + n) = o1;
        }
    }
}

// ---------------- RNN chunk: PULL model (local writes + cluster barrier + v4 pull) ----------------
// dynamic smem (bytes):
//   [0, 4352)          h ping-pong  [2][544]
//   [4352, 69888)      U slice      [<=256][64]
//   [69888, 135424)    g ring fp32  [<=256][64]
//   [135424, 168192)   qg ring bf16 [<=256][64]
#define RNN_SMEM 168192
__device__ __forceinline__ int padidx(int j) { return ((j >> 7) * 136) + (j & 127); }

__global__ void __cluster_dims__(8, 1, 1) __launch_bounds__(256, 1)
rnn_chunk(const float* __restrict__ W_hh, const float* __restrict__ U,
          const float* __restrict__ hin, float* __restrict__ hout,
          float* __restrict__ g_out, __nv_bfloat16* __restrict__ qgh,
          int t0, int nstep, float* __restrict__ h_lastp) {
    extern __shared__ char smraw[];
    float* h_sh = reinterpret_cast<float*>(smraw);
    float* U_s  = reinterpret_cast<float*>(smraw + 4352);
    float* g_s  = reinterpret_cast<float*>(smraw + 69888);
    __nv_bfloat16* q_s = reinterpret_cast<__nv_bfloat16*>(smraw + 135424);
    const int tid = threadIdx.x;
    const int r = tid >> 2, s = tid & 3;
    uint32_t rank; asm("mov.u32 %0, %%cluster_ctarank;" : "=r"(rank));
    const int grow = (int)rank * 64 + r;
    const uint32_t hbase = smem_u32(h_sh);

    // preload U slice: nstep x 64 floats
    {
        const float* src = U + (size_t)t0 * 512 + rank * 64;
        const uint32_t udst = smem_u32(U_s);
        for (int idx = tid; idx < nstep * 16; idx += 256) {
            int tl = idx >> 4, seg = idx & 15;
            cpa16(udst + (uint32_t)(tl * 256 + seg * 16),
                  src + (size_t)tl * 512 + seg * 4);
        }
        asm volatile("cp.async.commit_group;" ::: "memory");
    }

    ull w2[64];
    const float4* w4 = reinterpret_cast<const float4*>(W_hh + (size_t)grow * 512 + s * 128);
#pragma unroll
    for (int u = 0; u < 32; u++) {
        float4 v = w4[u];
        w2[2 * u]     = pack2(v.x, v.y);
        w2[2 * u + 1] = pack2(v.z, v.w);
    }
    for (int i = tid; i < 512; i += 256)
        h_sh[padidx(i)] = hin[i];
    asm volatile("cp.async.wait_group 0;" ::: "memory");
    __syncthreads();
    asm volatile("barrier.cluster.arrive.aligned;" ::: "memory");
    asm volatile("barrier.cluster.wait.aligned;" ::: "memory");

    // pull-phase addresses: threads 0..111 each fetch one 16B of one remote block
    uint32_t psrc0 = 0, psrc1 = 0, pdst0 = 0, pdst1 = 0;
    if (tid < 112) {
        int i = tid >> 4, v = tid & 15;
        uint32_t rc = (rank + 1u + (uint32_t)i) & 7u;
        uint32_t off = (uint32_t)padidx((int)rc * 64) * 4u + (uint32_t)v * 16u;
        pdst0 = hbase + off;
        pdst1 = hbase + 2176u + off;
        asm("mapa.shared::cluster.u32 %0, %1, %2;" : "=r"(psrc0) : "r"(pdst0), "r"(rc));
        asm("mapa.shared::cluster.u32 %0, %1, %2;" : "=r"(psrc1) : "r"(pdst1), "r"(rc));
    }
    const uint32_t lown0 = hbase + (uint32_t)padidx(grow) * 4u;          // own slot buf0
    const uint32_t lown1 = lown0 + 2176u;                                 // own slot buf1

    float uval = U_s[r];
    float hlast = 0.f;
    for (int tl = 0; tl < nstep; tl++) {
        const int cur = tl & 1;
        const ulonglong2* h4 = reinterpret_cast<const ulonglong2*>(&h_sh[cur * 544 + s * 136]);
        ull a0 = 0ULL, a1 = 0ULL, a2 = 0ULL, a3 = 0ULL;
#pragma unroll
        for (int u = 0; u < 32; u += 2) {
            ulonglong2 p = h4[u];
            ulonglong2 q = h4[u + 1];
            ffma2(a0, w2[2 * u],     p.x);
            ffma2(a1, w2[2 * u + 1], p.y);
            ffma2(a2, w2[2 * u + 2], q.x);
            ffma2(a3, w2[2 * u + 3], q.y);
        }
        float e, f, g2, h2v, i2, j2, k2, l2;
        unpack2(e, f, a0); unpack2(g2, h2v, a1);
        unpack2(i2, j2, a2); unpack2(k2, l2, a3);
        float sum = ((e + f) + (g2 + h2v)) + ((i2 + j2) + (k2 + l2));
        sum += __shfl_xor_sync(0xffffffffu, sum, 1);
        sum += __shfl_xor_sync(0xffffffffu, sum, 2);
        float hn = tanhf(uval + sum);             // all 4 sibling lanes
        if (s == 0) g_s[tl * 64 + r] = hn;
        if (s == 1) q_s[tl * 64 + r] = __float2bfloat16(hn);
        if (tl == nstep - 1) { hlast = hn; break; }
        // local write of own h into NEXT buffer, then cluster barrier (release)
        if (s == 2) {
            uint32_t la = cur ? lown0 : lown1;
            asm volatile("st.shared.f32 [%0], %1;" :: "r"(la), "f"(hn));
        }
        asm volatile("barrier.cluster.arrive.aligned;" ::: "memory");
        uval = U_s[(tl + 1) * 64 + r];            // hidden under barrier
        asm volatile("barrier.cluster.wait.aligned;" ::: "memory");
        // pull remote 448 values into NEXT buffer
        if (tid < 112) {
            uint32_t srcp = cur ? psrc0 : psrc1;
            uint32_t dstp = cur ? pdst0 : pdst1;
            uint32_t x0, x1, x2, x3;
            asm volatile("ld.shared::cluster.v4.b32 {%0,%1,%2,%3}, [%4];"
                         : "=r"(x0), "=r"(x1), "=r"(x2), "=r"(x3) : "r"(srcp));
            asm volatile("st.shared.v4.b32 [%0], {%1,%2,%3,%4};"
                         :: "r"(dstp), "r"(x0), "r"(x1), "r"(x2), "r"(x3));
        }
        __syncthreads();
    }

    __syncthreads();
    // bulk dump g (fp32) and qg (bf16) rings to global
    {
        const size_t gbase = (size_t)t0 * 512 + rank * 64;
        const float4* gsv = reinterpret_cast<const float4*>(g_s);
        for (int idx = tid; idx < nstep * 16; idx += 256) {
            int tl = idx >> 4, c4 = idx & 15;
            *reinterpret_cast<float4*>(g_out + gbase + (size_t)tl * 512 + c4 * 4) =
                gsv[tl * 16 + c4];
        }
        const uint4* qsv = reinterpret_cast<const uint4*>(q_s);
        for (int idx = tid; idx < nstep * 8; idx += 256) {
            int tl = idx >> 3, seg = idx & 7;
            *reinterpret_cast<uint4*>(
                reinterpret_cast<char*>(qgh + gbase + (size_t)tl * 512) + seg * 16) =
                qsv[tl * 8 + seg];
        }
    }
    if (s == 0) {
        hout[grow] = hlast;
        if (t0 + nstep == T_) h_lastp[grow] = hlast;
    }
}

// ---------------- gather with exact fp32 rescoring (row-chunkable) ----------------
#define DELTA 96.f
__global__ void __launch_bounds__(256, 1)
gather_ex(const float* __restrict__ L, const float* __restrict__ Q,
          const float* __restrict__ Kp, const float* __restrict__ nrm,
          const float* __restrict__ V, float* __restrict__ out, int row_base) {
    __shared__ float s_q[512];
    __shared__ int   s_idx[2048];
    __shared__ float s_e[2048];
    __shared__ float red[8];
    __shared__ float s_max, s_exm, s_den;
    __shared__ int   s_cnt;
    const int tid = threadIdx.x, wid = tid >> 5, lane = tid & 31;
    const int row = blockIdx.x + row_base;
    const float* Lr = L + (size_t)row * 32768;

    s_q[tid]       = Q[(size_t)row * 512 + tid];
    s_q[tid + 256] = Q[(size_t)row * 512 + tid + 256];
    if (tid == 0) { s_cnt = 0; s_den = 0.f; }

    float lm = -3.4e38f;
    const float4* L4 = reinterpret_cast<const float4*>(Lr);
#pragma unroll
    for (int i = 0; i < 32; i++) {
        float4 v = L4[tid + 256 * i];
        lm = fmaxf(fmaxf(lm, v.x), fmaxf(fmaxf(v.y, v.z), v.w));
    }
#pragma unroll
    for (int o = 16; o; o >>= 1) lm = fmaxf(lm, __shfl_xor_sync(0xffffffffu, lm, o));
    if (lane == 0) red[wid] = lm;
    __syncthreads();
    if (tid < 8) {
        float v = red[tid];
#pragma unroll
        for (int o = 4; o; o >>= 1) v = fmaxf(v, __shfl_xor_sync(0xffu, v, o));
        if (tid == 0) s_max = v;
    }
    __syncthreads();
    const float thr = s_max - DELTA;

    for (int i = 0; i < 32; i++) {
        float4 v = L4[tid + 256 * i];
        int b4 = (tid + 256 * i) << 2;
        if (v.x > thr) { int sl = atomicAdd(&s_cnt, 1); if (sl < 2048) s_idx[sl] = b4; }
        if (v.y > thr) { int sl = atomicAdd(&s_cnt, 1); if (sl < 2048) s_idx[sl] = b4 + 1; }
        if (v.z > thr) { int sl = atomicAdd(&s_cnt, 1); if (sl < 2048) s_idx[sl] = b4 + 2; }
        if (v.w > thr) { int sl = atomicAdd(&s_cnt, 1); if (sl < 2048) s_idx[sl] = b4 + 3; }
    }
    __syncthreads();
    const int cnt = min(s_cnt, 2048);

    for (int j = wid; j < cnt; j += 8) {
        int idx = s_idx[j];
        const float* Kr = Kp + (size_t)idx * 1024;
        float d = 0.f;
#pragma unroll
        for (int i = 0; i < 16; i++) d += s_q[lane + 32 * i] * Kr[lane + 32 * i];
#pragma unroll
        for (int o = 16; o; o >>= 1) d += __shfl_xor_sync(0xffffffffu, d, o);
        if (lane == 0) s_e[j] = 16.f * d - 8.f * nrm[idx];
    }
    __syncthreads();

    float em = -3.4e38f;
    for (int j = tid; j < cnt; j += 256) em = fmaxf(em, s_e[j]);
#pragma unroll
    for (int o = 16; o; o >>= 1) em = fmaxf(em, __shfl_xor_sync(0xffffffffu, em, o));
    if (lane == 0) red[wid] = em;
    __syncthreads();
    if (tid < 8) {
        float v = red[tid];
#pragma unroll
        for (int o = 4; o; o >>= 1) v = fmaxf(v, __shfl_xor_sync(0xffu, v, o));
        if (tid == 0) s_exm = v;
    }
    __syncthreads();
    const float exm = s_exm;
    float den = 0.f;
    for (int j = tid; j < cnt; j += 256) {
        float e = s_e[j];
        float p = (e > exm - 25.f) ? expf(e - exm) : 0.f;
        s_e[j] = p;
        den += p;
    }
#pragma unroll
    for (int o = 16; o; o >>= 1) den += __shfl_xor_sync(0xffffffffu, den, o);
    if (lane == 0 && den != 0.f) atomicAdd(&s_den, den);
    __syncthreads();

    float acc0 = 0.f, acc1 = 0.f;
    for (int j = 0; j < cnt; j++) {
        float p = s_e[j];
        if (p > 0.f) {
            const float* Vr = V + (size_t)s_idx[j] * 1024;
            acc0 += p * Vr[tid];
            acc1 += p * Vr[tid + 256];
        }
    }
    out[(size_t)row * 512 + tid]       = acc0 / s_den;
    out[(size_t)row * 512 + tid + 256] = acc1 / s_den;
}

// ---------------- launch ----------------
extern "C" void kernel_launch(void* const* d_in, const int* in_sizes, int n_in,
                              void* d_out, int out_size) {
    const float* inp   = (const float*)d_in[0];
    const float* x_obs = (const float*)d_in[1];
    const float* patt  = (const float*)d_in[2];
    const float* h0    = (const float*)d_in[3];
    const float* W_ih  = (const float*)d_in[4];
    const float* W_hh  = (const float*)d_in[5];
    const float* b_ih  = (const float*)d_in[6];
    const float* b_hh  = (const float*)d_in[7];

    float* out     = (float*)d_out;
    float* prob_g  = out;
    float* prob_x  = out + 1024 * 512;
    float* g_cur   = out + 2 * 1024 * 512;
    float* h_lastp = out + 3 * 1024 * 512;

    float *U, *Lx, *Lg, *nx, *ng, *bs, *hst;
    __nv_bfloat16 *xvh, *gkh, *qxh, *qgh;
    cudaGetSymbolAddress((void**)&U,  d_U);
    cudaGetSymbolAddress((void**)&Lx, d_Lx);
    cudaGetSymbolAddress((void**)&Lg, d_Lg);
    cudaGetSymbolAddress((void**)&nx, d_nx);
    cudaGetSymbolAddress((void**)&ng, d_ng);
    cudaGetSymbolAddress((void**)&bs, d_bsum);
    cudaGetSymbolAddress((void**)&hst, d_hstate);
    cudaGetSymbolAddress((void**)&xvh, d_xv_hi);
    cudaGetSymbolAddress((void**)&gkh, d_gk_hi);
    cudaGetSymbolAddress((void**)&qxh, d_qx_hi);
    cudaGetSymbolAddress((void**)&qgh, d_qg_hi);

    const int smemGemm = 2 * 2 * 128 * PADK * 4;   // 73728
    const int smem1p   = 4 * STG1;                 // 81920

    static int inited = 0;
    static cudaStream_t s1, s2;
    static cudaEvent_t evFork, evPrep, evX, evG;
    static cudaEvent_t evR[5];
    if (!inited) {
        cudaFuncSetAttribute(gemm_nt, cudaFuncAttributeMaxDynamicSharedMemorySize, smemGemm);
        cudaFuncSetAttribute(gemm1p, cudaFuncAttributeMaxDynamicSharedMemorySize, smem1p);
        cudaFuncSetAttribute(rnn_chunk, cudaFuncAttributeMaxDynamicSharedMemorySize, RNN_SMEM);
        cudaStreamCreateWithFlags(&s1, cudaStreamNonBlocking);
        cudaStreamCreateWithFlags(&s2, cudaStreamNonBlocking);
        cudaEventCreateWithFlags(&evFork, cudaEventDisableTiming);
        cudaEventCreateWithFlags(&evPrep, cudaEventDisableTiming);
        cudaEventCreateWithFlags(&evX, cudaEventDisableTiming);
        cudaEventCreateWithFlags(&evG, cudaEventDisableTiming);
        for (int i = 0; i < 5; i++) cudaEventCreateWithFlags(&evR[i], cudaEventDisableTiming);
        inited = 1;
    }

    cudaEventRecord(evFork, 0);
    cudaStreamWaitEvent(s1, evFork, 0);
    cudaStreamWaitEvent(s2, evFork, 0);

    // chunk schedule: 3x256 + 2x128 (smaller serial tail)
    const int cst[5]  = {0, 256, 512, 768, 896};
    const int clen[5] = {256, 256, 256, 128, 128};

    // ---- main: U -> 5 RNN chunks (enqueued FIRST for dispatch priority) ----
    bsum_kernel<<<1, 512>>>(b_ih, b_hh, bs);
    gemm_nt<<<dim3(8, 4), 256, smemGemm>>>(inp, 128, W_ih, 128, bs, 1.f, 1.f, U, 512, 128);
    for (int c = 0; c < 5; c++) {
        rnn_chunk<<<8, 256, RNN_SMEM>>>(W_hh, U, (c == 0) ? h0 : hst, hst,
                                        g_cur, qgh, cst[c], clen[c], h_lastp);
        cudaEventRecord(evR[c], 0);
    }

    // ---- s1: x-retrieval chain ----
    prep_patterns<<<M_, 256, 0, s1>>>(patt, xvh, gkh, nx, ng);
    cudaEventRecord(evPrep, s1);
    split_q<<<1024, 128, 0, s1>>>(x_obs, qxh);
    gemm1p<<<2048, 256, smem1p, s1>>>(qxh, xvh, nx, 16.f, -8.f, Lx, 32768, 8, 0);
    gather_ex<<<1024, 256, 0, s1>>>(Lx, x_obs, patt, nx, patt, prob_x, 0);
    cudaEventRecord(evX, s1);

    // ---- s2: g-retrieval pipelined over RNN chunks ----
    cudaStreamWaitEvent(s2, evPrep, 0);
    for (int c = 0; c < 5; c++) {
        cudaStreamWaitEvent(s2, evR[c], 0);
        int span = clen[c] >> 7;
        gemm1p<<<span * 256, 256, smem1p, s2>>>(qgh, gkh, ng, 16.f, -8.f, Lg, 32768,
                                                span, cst[c] >> 7);
        gather_ex<<<clen[c], 256, 0, s2>>>(Lg, g_cur, patt + 512, ng, patt, prob_g, cst[c]);
    }
    cudaEventRecord(evG, s2);

    cudaStreamWaitEvent(0, evX, 0);
    cudaStreamWaitEvent(0, evG, 0);
}